// round 15
// baseline (speedup 1.0000x reference)
#include <cuda_runtime.h>
#include <cuda_fp16.h>
#include <cstdint>
#include <cstddef>

// ---------------------------------------------------------------------------
// StructuredStateRecurrence (sm_103 base -> legacy mma.sync path, fp16 HMMA).
//   v = x @ Wv^T + bv ; s_t = td*s_{t-1} + v_t ; wv = s + ms*tf
//   out = x + [x | wv] @ Wg^T + bg ; next_ms = wv[:, -1]
// k = x@Wk+bk is dead code in the reference -> skipped.
// R14: isolation round. GEMM = R13's 6-stage pipeline (measured: GEMM1
//      112.8 -> 106.2us, tensor 53.1%). Scan = R12's 3-kernel form
//      (local/carry/apply) restored — R13's fused carry made the last
//      chunk's block tail-heavy (127-step serial fma chain per block).
// Shapes: B=4, S=4096, D=2048, M=512.
// ---------------------------------------------------------------------------

#define B_  4
#define S_  4096
#define D_  2048
#define M_  512
#define BSR (B_ * S_)        // 16384 GEMM rows
#define CCH 128              // scan chunks
#define LCH (S_ / CCH)       // 32 steps per chunk

__device__ float  g_wv[(size_t)B_ * S_ * M_];      // fp32 v / scanned s
__device__ __half g_wv_h[(size_t)B_ * S_ * M_];    // fp16 wv for GEMM2
__device__ __half g_xh[(size_t)BSR * D_];          // fp16 x
__device__ __half g_Wvh[(size_t)M_ * D_];          // fp16 Wv
__device__ __half g_Wgh[(size_t)D_ * (D_ + M_)];   // fp16 Wg
__device__ float  g_carry[B_ * CCH * M_];
__device__ float  g_prefix[B_ * CCH * M_];

// ---------------- helpers ----------------
__device__ __forceinline__ unsigned pack_h2(float a, float b) {
    unsigned u;
    asm("cvt.rn.f16x2.f32 %0, %2, %1;" : "=r"(u) : "f"(a), "f"(b));
    return u;
}
__device__ __forceinline__ uint32_t smem_u32(const void* p) {
    uint32_t a;
    asm("{ .reg .u64 t; cvta.to.shared.u64 t, %1; cvt.u32.u64 %0, t; }"
        : "=r"(a) : "l"(p));
    return a;
}
__device__ __forceinline__ void cp16(uint32_t dst, const void* src) {
    asm volatile("cp.async.cg.shared.global [%0], [%1], 16;"
                 :: "r"(dst), "l"(src));
}
__device__ __forceinline__ void cp_commit() {
    asm volatile("cp.async.commit_group;");
}
__device__ __forceinline__ void cp_wait4() {
    asm volatile("cp.async.wait_group 4;");
}
__device__ __forceinline__ void ldsm4(unsigned& r0, unsigned& r1,
                                      unsigned& r2, unsigned& r3, unsigned addr) {
    asm volatile("ldmatrix.sync.aligned.m8n8.x4.shared.b16 {%0,%1,%2,%3}, [%4];"
                 : "=r"(r0), "=r"(r1), "=r"(r2), "=r"(r3) : "r"(addr));
}
__device__ __forceinline__ void mma_fp16(float (&c)[4], const unsigned (&a)[4],
                                         const unsigned (&b)[2]) {
    asm volatile(
        "mma.sync.aligned.m16n8k16.row.col.f32.f16.f16.f32 "
        "{%0,%1,%2,%3}, {%4,%5,%6,%7}, {%8,%9}, {%0,%1,%2,%3};\n"
        : "+f"(c[0]), "+f"(c[1]), "+f"(c[2]), "+f"(c[3])
        : "r"(a[0]), "r"(a[1]), "r"(a[2]), "r"(a[3]), "r"(b[0]), "r"(b[1]));
}
__device__ __forceinline__ float sigmoidf_(float t) {
    return 1.0f / (1.0f + expf(-t));
}

// fp32 -> fp16 bulk convert (n multiple of 8)
__global__ __launch_bounds__(256)
void cvt_f2h(const float* __restrict__ s, __half* __restrict__ d, int n) {
    int i = (blockIdx.x * 256 + threadIdx.x) * 8;
    if (i >= n) return;
    float4 a = *(const float4*)(s + i);
    float4 b = *(const float4*)(s + i + 4);
    *(uint4*)(d + i) = make_uint4(pack_h2(a.x, a.y), pack_h2(a.z, a.w),
                                  pack_h2(b.x, b.y), pack_h2(b.z, b.w));
}

// ---------------------------------------------------------------------------
// fp16 GEMM: C[row,n] = sum_k A[row,k]*Bm[n,k] + bias[n] (+ resid[row,n])
// A = virtual concat A1(K1)|A2 (K-tiles of 32 never straddle; K1 % 32 == 0).
// CTA tile 128x128, BK=32, 256 threads (8 warps, 2x4), warp tile 64x32
// (4x4 m16n8k16 frags), fp32 acc, occupancy 2. 6-stage cp.async pipeline
// (wait_group 4 -> 4 tiles of latency slack); stage = A[128][32h] (8KB) +
// B[128][32h] (8KB) = 16KB. Row = 64B = 4 x 16B chunks, chunk swizzle
// c ^= (row>>1)&3; fragments via ldmatrix.x4; cp.async issue interleaved
// between the two k16 compute halves.
// ---------------------------------------------------------------------------
template <bool HAS_A2, bool HAS_RES>
__global__ __launch_bounds__(256, 2)
void gemm_h(const __half* __restrict__ A1, int lda1, int K1,
            const __half* __restrict__ A2, int lda2,
            const __half* __restrict__ Bm,    // [N, Ktot] half, row-major
            const float* __restrict__ bias,   // [N]
            const float* __restrict__ resid, int ldr,
            float* __restrict__ Cout, int ldc, int Ktot)
{
    constexpr int STG = 6;                  // 6 x 16KB = 96KB dynamic smem
    extern __shared__ uint4 dsm4[];
    unsigned* smem = (unsigned*)dsm4;
    const unsigned sbase = smem_u32(smem);

    const int tid = threadIdx.x;
    const int lane = tid & 31;
    const int warp = tid >> 5;
    const int wm = (warp & 1) * 64;
    const int wn = (warp >> 1) * 32;
    const int rowBlock = blockIdx.y * 128;
    const int colBlock = blockIdx.x * 128;
    const int KT = Ktot / 32;

    // cp.async geometry: thread -> (row r, K-half h); 2 x 16B for A, 2 for B
    const int r = tid >> 1;       // 0..127
    const int h = tid & 1;        // 0..1
    const int swz = (r >> 1) & 3;
    const unsigned dA0 = sbase + (unsigned)(r * 64 + (((2 * h) ^ swz) << 4));
    const unsigned dA1 = sbase + (unsigned)(r * 64 + (((2 * h + 1) ^ swz) << 4));

    // ldmatrix per-lane geometry (j = lane>>3 selects the 8x8 matrix):
    //   A matrices: (r0,k-even),(r8,k-even),(r0,k-odd),(r8,k-odd)
    //   B matrices: (n0,k-even),(n0,k-odd),(n8,k-even),(n8,k-odd) per p
    const int lrow8 = lane & 7;
    unsigned offA[4], swzA[4];
#pragma unroll
    for (int mi = 0; mi < 4; ++mi) {
        const int rowA = wm + mi * 16 + (((lane >> 3) & 1) << 3) + lrow8;
        offA[mi] = (unsigned)(rowA * 64);
        swzA[mi] = (unsigned)((rowA >> 1) & 3);
    }
    const unsigned kselA = (unsigned)(lane >> 4);
    unsigned offB[2], swzB[2];
#pragma unroll
    for (int p = 0; p < 2; ++p) {
        const int rowB = wn + ((2 * p + (lane >> 4)) << 3) + lrow8;
        offB[p] = (unsigned)(rowB * 64);
        swzB[p] = (unsigned)((rowB >> 1) & 3);
    }
    const unsigned kselB = (unsigned)((lane >> 3) & 1);

    float acc[4][4][4];
#pragma unroll
    for (int i = 0; i < 4; ++i)
#pragma unroll
        for (int j = 0; j < 4; ++j)
#pragma unroll
            for (int q = 0; q < 4; ++q) acc[i][j][q] = 0.0f;

    auto issue = [&](int slot, int kt) {
        const int kBase = kt * 32;
        const __half* Ap = A1;
        int lda = lda1, kl = kBase;
        if (HAS_A2 && kBase >= K1) { Ap = A2; lda = lda2; kl = kBase - K1; }
        const char* ga = (const char*)(Ap + (size_t)(rowBlock + r) * lda + kl + h * 16);
        const char* gb = (const char*)(Bm + (size_t)(colBlock + r) * Ktot + kBase + h * 16);
        const unsigned so = (unsigned)(slot * 16384);
        cp16(dA0 + so, ga);
        cp16(dA1 + so, ga + 16);
        cp16(dA0 + so + 8192, gb);
        cp16(dA1 + so + 8192, gb + 16);
    };

    // one k16 step (ks in 0..1) of the K-tile in `slot`
    auto compute_ks = [&](int slot, int ks) {
        const unsigned baseA = sbase + (unsigned)(slot * 16384);
        const unsigned baseB = baseA + 8192u;
        const unsigned kgA = 2u * (unsigned)ks + kselA;
        const unsigned kgB = 2u * (unsigned)ks + kselB;
        unsigned a[4][4], bfr[4][2];
#pragma unroll
        for (int mi = 0; mi < 4; ++mi)
            ldsm4(a[mi][0], a[mi][1], a[mi][2], a[mi][3],
                  baseA + offA[mi] + ((kgA ^ swzA[mi]) << 4));
#pragma unroll
        for (int p = 0; p < 2; ++p)
            ldsm4(bfr[2 * p][0], bfr[2 * p][1], bfr[2 * p + 1][0], bfr[2 * p + 1][1],
                  baseB + offB[p] + ((kgB ^ swzB[p]) << 4));
#pragma unroll
        for (int mi = 0; mi < 4; ++mi)
#pragma unroll
            for (int ni = 0; ni < 4; ++ni) mma_fp16(acc[mi][ni], a[mi], bfr[ni]);
    };

    // prologue: stages 0..4
#pragma unroll
    for (int s = 0; s < STG - 1; ++s) { issue(s, s); cp_commit(); }

    for (int kt = 0; kt < KT; ++kt) {
        cp_wait4();            // committed = 5+kt; pending <=4 -> tile kt done
        __syncthreads();       // also protects slot reuse
        const int cur = kt % STG;
        // first k16 half starts the MMA stream immediately...
        compute_ks(cur, 0);
        // ...then next tile's cp.async issue dual-issues under the MMAs
        const int pf = kt + STG - 1;
        if (pf < KT) issue(pf % STG, pf);
        cp_commit();
        compute_ks(cur, 1);
    }

    // epilogue: bias + optional residual, float2 stores (col even -> aligned)
#pragma unroll
    for (int mi = 0; mi < 4; ++mi) {
#pragma unroll
        for (int ni = 0; ni < 4; ++ni) {
            const int row = rowBlock + wm + mi * 16 + (lane >> 2);
            const int col = colBlock + wn + ni * 8 + (lane & 3) * 2;
            const float b0v = bias[col];
            const float b1v = bias[col + 1];
            float r00 = 0.f, r01 = 0.f, r10 = 0.f, r11 = 0.f;
            if (HAS_RES) {
                const float2 q0 = *(const float2*)(resid + (size_t)row * ldr + col);
                const float2 q1 = *(const float2*)(resid + (size_t)(row + 8) * ldr + col);
                r00 = q0.x; r01 = q0.y; r10 = q1.x; r11 = q1.y;
            }
            *(float2*)(Cout + (size_t)row * ldc + col) =
                make_float2(acc[mi][ni][0] + b0v + r00, acc[mi][ni][1] + b1v + r01);
            *(float2*)(Cout + (size_t)(row + 8) * ldc + col) =
                make_float2(acc[mi][ni][2] + b0v + r10, acc[mi][ni][3] + b1v + r11);
        }
    }
}

// ---------------------------------------------------------------------------
// Chunked linear-recurrence scan (3 passes, R12 form).
// ---------------------------------------------------------------------------
__global__ __launch_bounds__(M_)
void scan_local_kernel(const float* __restrict__ td_raw)
{
    const int m = threadIdx.x;
    const int c = blockIdx.x;
    const int b = blockIdx.y;
    const float td = sigmoidf_(td_raw[m]) * 0.9f + 0.1f;
    size_t base = ((size_t)(b * S_ + c * LCH)) * M_ + m;
    float s = 0.0f;
#pragma unroll 4
    for (int i = 0; i < LCH; ++i) {
        const float v = g_wv[base + (size_t)i * M_];
        s = fmaf(td, s, v);
        g_wv[base + (size_t)i * M_] = s;
    }
    g_carry[(b * CCH + c) * M_ + m] = s;
}

__global__ __launch_bounds__(M_)
void scan_carry_kernel(const float* __restrict__ td_raw)
{
    const int m = threadIdx.x;
    const int b = blockIdx.x;
    const float td = sigmoidf_(td_raw[m]) * 0.9f + 0.1f;
    const float tdL = powf(td, (float)LCH);
    float G = 0.0f;
    for (int c = 0; c < CCH; ++c) {
        const int idx = (b * CCH + c) * M_ + m;
        g_prefix[idx] = G;
        G = fmaf(tdL, G, g_carry[idx]);
    }
}

// wv = local + P*td^(i+1) + ms*tf -> fp16 for GEMM2; nms (fp32) at t=S-1
__global__ __launch_bounds__(M_)
void scan_apply_kernel(const float* __restrict__ td_raw,
                       const float* __restrict__ tf_raw,
                       const float* __restrict__ ms,
                       float* __restrict__ nms)
{
    const int m = threadIdx.x;
    const int c = blockIdx.x;
    const int b = blockIdx.y;
    const float td = sigmoidf_(td_raw[m]) * 0.9f + 0.1f;
    const float tf = sigmoidf_(tf_raw[m]);
    const float msterm = ms[b * M_ + m] * tf;
    const float P = g_prefix[(b * CCH + c) * M_ + m];
    size_t base = ((size_t)(b * S_ + c * LCH)) * M_ + m;
    float pw = td;
    float w = 0.0f;
#pragma unroll 4
    for (int i = 0; i < LCH; ++i) {
        w = g_wv[base + (size_t)i * M_] + P * pw + msterm;
        g_wv_h[base + (size_t)i * M_] = __float2half(w);
        pw *= td;
    }
    if (nms != nullptr && c == CCH - 1) nms[b * M_ + m] = w;
}

// ---------------------------------------------------------------------------
extern "C" void kernel_launch(void* const* d_in, const int* in_sizes, int n_in,
                              void* d_out, int out_size)
{
    const float* x   = (const float*)d_in[0];
    const float* ms  = (const float*)d_in[1];
    // d_in[2]=Wk, d_in[3]=bk: dead in the reference, intentionally unused
    const float* Wv  = (const float*)d_in[4];
    const float* bv  = (const float*)d_in[5];
    const float* Wg  = (const float*)d_in[6];
    const float* bg  = (const float*)d_in[7];
    const float* tdr = (const float*)d_in[8];
    const float* tfr = (const float*)d_in[9];
    float* out = (float*)d_out;

    float*  wv_ptr  = nullptr;
    __half* wvh_ptr = nullptr;
    __half* xh_ptr  = nullptr;
    __half* Wvh_ptr = nullptr;
    __half* Wgh_ptr = nullptr;
    cudaGetSymbolAddress((void**)&wv_ptr,  g_wv);
    cudaGetSymbolAddress((void**)&wvh_ptr, g_wv_h);
    cudaGetSymbolAddress((void**)&xh_ptr,  g_xh);
    cudaGetSymbolAddress((void**)&Wvh_ptr, g_Wvh);
    cudaGetSymbolAddress((void**)&Wgh_ptr, g_Wgh);

    const int DSMEM = 6 * 16384;  // 96KB per CTA, 192KB/SM at occupancy 2
    cudaFuncSetAttribute((const void*)gemm_h<false, false>,
                         cudaFuncAttributeMaxDynamicSharedMemorySize, DSMEM);
    cudaFuncSetAttribute((const void*)gemm_h<true, true>,
                         cudaFuncAttributeMaxDynamicSharedMemorySize, DSMEM);

    // 0) fp32 -> fp16 operand conversion
    const int nx = BSR * D_, nwv = M_ * D_, nwg = D_ * (D_ + M_);
    cvt_f2h<<<(nx  + 2047) / 2048, 256>>>(x,  xh_ptr,  nx);
    cvt_f2h<<<(nwv + 2047) / 2048, 256>>>(Wv, Wvh_ptr, nwv);
    cvt_f2h<<<(nwg + 2047) / 2048, 256>>>(Wg, Wgh_ptr, nwg);

    // 1) v = x @ Wv^T + bv  -> g_wv (fp32)   [16384 x 512], K=2048
    gemm_h<false, false><<<dim3(M_ / 128, BSR / 128), 256, DSMEM>>>(
        xh_ptr, D_, D_, nullptr, 0, Wvh_ptr, bv, nullptr, 0, wv_ptr, M_, D_);

    // 2) chunked scan + ms*tf -> g_wv_h (fp16), emits next_memory_state
    const size_t bsd = (size_t)B_ * S_ * D_;
    float* nms = ((size_t)out_size >= bsd + (size_t)B_ * M_) ? out + bsd : nullptr;
    scan_local_kernel<<<dim3(CCH, B_), M_>>>(tdr);
    scan_carry_kernel<<<B_, M_>>>(tdr);
    scan_apply_kernel<<<dim3(CCH, B_), M_>>>(tdr, tfr, ms, nms);

    // 3) out = x + [x | wv] @ Wg^T + bg   [16384 x 2048], K=2560 (2048+512)
    gemm_h<true, true><<<dim3(D_ / 128, BSR / 128), 256, DSMEM>>>(
        xh_ptr, D_, D_, wvh_ptr, M_, Wgh_ptr, bg, x, D_, out, D_, D_ + M_);
}

// round 16
// speedup vs baseline: 1.0870x; 1.0870x over previous
#include <cuda_runtime.h>
#include <cuda_fp16.h>
#include <cstdint>
#include <cstddef>

// ---------------------------------------------------------------------------
// StructuredStateRecurrence (sm_103 base -> legacy mma.sync path, fp16 HMMA).
//   v = x @ Wv^T + bv ; s_t = td*s_{t-1} + v_t ; wv = s + ms*tf
//   out = x + [x | wv] @ Wg^T + bg ; next_ms = wv[:, -1]
// k = x@Wk+bk is dead code in the reference -> skipped.
// R15: assembly of measured-best axes from the R12/R13/R14 decomposition:
//      GEMM1 = 6-stage pipeline (measured -6.4us), GEMM2 = 4-stage
//      (6-stage cost GEMM2 ~+36us), scan = fused 2-kernel form
//      (measured -18.5us). Stage count is a template parameter.
// Shapes: B=4, S=4096, D=2048, M=512.
// ---------------------------------------------------------------------------

#define B_  4
#define S_  4096
#define D_  2048
#define M_  512
#define BSR (B_ * S_)        // 16384 GEMM rows
#define CCH 128              // scan chunks
#define LCH (S_ / CCH)       // 32 steps per chunk

__device__ float  g_wv[(size_t)B_ * S_ * M_];      // fp32 v / scanned s
__device__ __half g_wv_h[(size_t)B_ * S_ * M_];    // fp16 wv for GEMM2
__device__ __half g_xh[(size_t)BSR * D_];          // fp16 x
__device__ __half g_Wvh[(size_t)M_ * D_];          // fp16 Wv
__device__ __half g_Wgh[(size_t)D_ * (D_ + M_)];   // fp16 Wg
__device__ float  g_carry[B_ * CCH * M_];

// ---------------- helpers ----------------
__device__ __forceinline__ unsigned pack_h2(float a, float b) {
    unsigned u;
    asm("cvt.rn.f16x2.f32 %0, %2, %1;" : "=r"(u) : "f"(a), "f"(b));
    return u;
}
__device__ __forceinline__ uint32_t smem_u32(const void* p) {
    uint32_t a;
    asm("{ .reg .u64 t; cvta.to.shared.u64 t, %1; cvt.u32.u64 %0, t; }"
        : "=r"(a) : "l"(p));
    return a;
}
__device__ __forceinline__ void cp16(uint32_t dst, const void* src) {
    asm volatile("cp.async.cg.shared.global [%0], [%1], 16;"
                 :: "r"(dst), "l"(src));
}
__device__ __forceinline__ void cp_commit() {
    asm volatile("cp.async.commit_group;");
}
template <int N>
__device__ __forceinline__ void cp_wait() {
    asm volatile("cp.async.wait_group %0;" :: "n"(N));
}
__device__ __forceinline__ void ldsm4(unsigned& r0, unsigned& r1,
                                      unsigned& r2, unsigned& r3, unsigned addr) {
    asm volatile("ldmatrix.sync.aligned.m8n8.x4.shared.b16 {%0,%1,%2,%3}, [%4];"
                 : "=r"(r0), "=r"(r1), "=r"(r2), "=r"(r3) : "r"(addr));
}
__device__ __forceinline__ void mma_fp16(float (&c)[4], const unsigned (&a)[4],
                                         const unsigned (&b)[2]) {
    asm volatile(
        "mma.sync.aligned.m16n8k16.row.col.f32.f16.f16.f32 "
        "{%0,%1,%2,%3}, {%4,%5,%6,%7}, {%8,%9}, {%0,%1,%2,%3};\n"
        : "+f"(c[0]), "+f"(c[1]), "+f"(c[2]), "+f"(c[3])
        : "r"(a[0]), "r"(a[1]), "r"(a[2]), "r"(a[3]), "r"(b[0]), "r"(b[1]));
}
__device__ __forceinline__ float sigmoidf_(float t) {
    return 1.0f / (1.0f + expf(-t));
}

// fp32 -> fp16 bulk convert (n multiple of 8)
__global__ __launch_bounds__(256)
void cvt_f2h(const float* __restrict__ s, __half* __restrict__ d, int n) {
    int i = (blockIdx.x * 256 + threadIdx.x) * 8;
    if (i >= n) return;
    float4 a = *(const float4*)(s + i);
    float4 b = *(const float4*)(s + i + 4);
    *(uint4*)(d + i) = make_uint4(pack_h2(a.x, a.y), pack_h2(a.z, a.w),
                                  pack_h2(b.x, b.y), pack_h2(b.z, b.w));
}

// ---------------------------------------------------------------------------
// fp16 GEMM: C[row,n] = sum_k A[row,k]*Bm[n,k] + bias[n] (+ resid[row,n])
// A = virtual concat A1(K1)|A2 (K-tiles of 32 never straddle; K1 % 32 == 0).
// CTA tile 128x128, BK=32, 256 threads (8 warps, 2x4), warp tile 64x32
// (4x4 m16n8k16 frags), fp32 acc, occupancy 2. STG-stage cp.async pipeline
// (wait_group STG-2); stage = A[128][32h] (8KB) + B[128][32h] (8KB) = 16KB.
// Row = 64B = 4 x 16B chunks, chunk swizzle c ^= (row>>1)&3; fragments via
// ldmatrix.x4; cp.async issue interleaved between the two k16 halves.
// ---------------------------------------------------------------------------
template <int STG, bool HAS_A2, bool HAS_RES>
__global__ __launch_bounds__(256, 2)
void gemm_h(const __half* __restrict__ A1, int lda1, int K1,
            const __half* __restrict__ A2, int lda2,
            const __half* __restrict__ Bm,    // [N, Ktot] half, row-major
            const float* __restrict__ bias,   // [N]
            const float* __restrict__ resid, int ldr,
            float* __restrict__ Cout, int ldc, int Ktot)
{
    extern __shared__ uint4 dsm4[];
    unsigned* smem = (unsigned*)dsm4;
    const unsigned sbase = smem_u32(smem);

    const int tid = threadIdx.x;
    const int lane = tid & 31;
    const int warp = tid >> 5;
    const int wm = (warp & 1) * 64;
    const int wn = (warp >> 1) * 32;
    const int rowBlock = blockIdx.y * 128;
    const int colBlock = blockIdx.x * 128;
    const int KT = Ktot / 32;

    // cp.async geometry: thread -> (row r, K-half h); 2 x 16B for A, 2 for B
    const int r = tid >> 1;       // 0..127
    const int h = tid & 1;        // 0..1
    const int swz = (r >> 1) & 3;
    const unsigned dA0 = sbase + (unsigned)(r * 64 + (((2 * h) ^ swz) << 4));
    const unsigned dA1 = sbase + (unsigned)(r * 64 + (((2 * h + 1) ^ swz) << 4));

    // ldmatrix per-lane geometry (j = lane>>3 selects the 8x8 matrix):
    //   A matrices: (r0,k-even),(r8,k-even),(r0,k-odd),(r8,k-odd)
    //   B matrices: (n0,k-even),(n0,k-odd),(n8,k-even),(n8,k-odd) per p
    const int lrow8 = lane & 7;
    unsigned offA[4], swzA[4];
#pragma unroll
    for (int mi = 0; mi < 4; ++mi) {
        const int rowA = wm + mi * 16 + (((lane >> 3) & 1) << 3) + lrow8;
        offA[mi] = (unsigned)(rowA * 64);
        swzA[mi] = (unsigned)((rowA >> 1) & 3);
    }
    const unsigned kselA = (unsigned)(lane >> 4);
    unsigned offB[2], swzB[2];
#pragma unroll
    for (int p = 0; p < 2; ++p) {
        const int rowB = wn + ((2 * p + (lane >> 4)) << 3) + lrow8;
        offB[p] = (unsigned)(rowB * 64);
        swzB[p] = (unsigned)((rowB >> 1) & 3);
    }
    const unsigned kselB = (unsigned)((lane >> 3) & 1);

    float acc[4][4][4];
#pragma unroll
    for (int i = 0; i < 4; ++i)
#pragma unroll
        for (int j = 0; j < 4; ++j)
#pragma unroll
            for (int q = 0; q < 4; ++q) acc[i][j][q] = 0.0f;

    auto issue = [&](int slot, int kt) {
        const int kBase = kt * 32;
        const __half* Ap = A1;
        int lda = lda1, kl = kBase;
        if (HAS_A2 && kBase >= K1) { Ap = A2; lda = lda2; kl = kBase - K1; }
        const char* ga = (const char*)(Ap + (size_t)(rowBlock + r) * lda + kl + h * 16);
        const char* gb = (const char*)(Bm + (size_t)(colBlock + r) * Ktot + kBase + h * 16);
        const unsigned so = (unsigned)(slot * 16384);
        cp16(dA0 + so, ga);
        cp16(dA1 + so, ga + 16);
        cp16(dA0 + so + 8192, gb);
        cp16(dA1 + so + 8192, gb + 16);
    };

    // one k16 step (ks in 0..1) of the K-tile in `slot`
    auto compute_ks = [&](int slot, int ks) {
        const unsigned baseA = sbase + (unsigned)(slot * 16384);
        const unsigned baseB = baseA + 8192u;
        const unsigned kgA = 2u * (unsigned)ks + kselA;
        const unsigned kgB = 2u * (unsigned)ks + kselB;
        unsigned a[4][4], bfr[4][2];
#pragma unroll
        for (int mi = 0; mi < 4; ++mi)
            ldsm4(a[mi][0], a[mi][1], a[mi][2], a[mi][3],
                  baseA + offA[mi] + ((kgA ^ swzA[mi]) << 4));
#pragma unroll
        for (int p = 0; p < 2; ++p)
            ldsm4(bfr[2 * p][0], bfr[2 * p][1], bfr[2 * p + 1][0], bfr[2 * p + 1][1],
                  baseB + offB[p] + ((kgB ^ swzB[p]) << 4));
#pragma unroll
        for (int mi = 0; mi < 4; ++mi)
#pragma unroll
            for (int ni = 0; ni < 4; ++ni) mma_fp16(acc[mi][ni], a[mi], bfr[ni]);
    };

    // prologue: stages 0..STG-2
#pragma unroll
    for (int s = 0; s < STG - 1; ++s) { issue(s, s); cp_commit(); }

    for (int kt = 0; kt < KT; ++kt) {
        cp_wait<STG - 2>();    // pending <= STG-2 -> tile kt resident
        __syncthreads();       // also protects slot reuse
        const int cur = kt % STG;
        // first k16 half starts the MMA stream immediately...
        compute_ks(cur, 0);
        // ...then next tile's cp.async issue dual-issues under the MMAs
        const int pf = kt + STG - 1;
        if (pf < KT) issue(pf % STG, pf);
        cp_commit();
        compute_ks(cur, 1);
    }

    // epilogue: bias + optional residual, float2 stores (col even -> aligned)
#pragma unroll
    for (int mi = 0; mi < 4; ++mi) {
#pragma unroll
        for (int ni = 0; ni < 4; ++ni) {
            const int row = rowBlock + wm + mi * 16 + (lane >> 2);
            const int col = colBlock + wn + ni * 8 + (lane & 3) * 2;
            const float b0v = bias[col];
            const float b1v = bias[col + 1];
            float r00 = 0.f, r01 = 0.f, r10 = 0.f, r11 = 0.f;
            if (HAS_RES) {
                const float2 q0 = *(const float2*)(resid + (size_t)row * ldr + col);
                const float2 q1 = *(const float2*)(resid + (size_t)(row + 8) * ldr + col);
                r00 = q0.x; r01 = q0.y; r10 = q1.x; r11 = q1.y;
            }
            *(float2*)(Cout + (size_t)row * ldc + col) =
                make_float2(acc[mi][ni][0] + b0v + r00, acc[mi][ni][1] + b1v + r01);
            *(float2*)(Cout + (size_t)(row + 8) * ldc + col) =
                make_float2(acc[mi][ni][2] + b0v + r10, acc[mi][ni][3] + b1v + r11);
        }
    }
}

// ---------------------------------------------------------------------------
// Chunked linear-recurrence scan (2 passes, fused carry — measured -18.5us).
// Pass A: per-chunk local scan, emits chunk-end carries.
// Pass B: each block redundantly scans the carries of chunks < c (identical
// fma order to a dedicated carry kernel), applies prefix + ms*tf, writes
// fp16 wv.
// ---------------------------------------------------------------------------
__global__ __launch_bounds__(M_)
void scan_local_kernel(const float* __restrict__ td_raw)
{
    const int m = threadIdx.x;
    const int c = blockIdx.x;
    const int b = blockIdx.y;
    const float td = sigmoidf_(td_raw[m]) * 0.9f + 0.1f;
    size_t base = ((size_t)(b * S_ + c * LCH)) * M_ + m;
    float s = 0.0f;
#pragma unroll 4
    for (int i = 0; i < LCH; ++i) {
        const float v = g_wv[base + (size_t)i * M_];
        s = fmaf(td, s, v);
        g_wv[base + (size_t)i * M_] = s;
    }
    g_carry[(b * CCH + c) * M_ + m] = s;
}

// wv = local + P*td^(i+1) + ms*tf -> fp16 for GEMM2; nms (fp32) at t=S-1
__global__ __launch_bounds__(M_)
void scan_apply_kernel(const float* __restrict__ td_raw,
                       const float* __restrict__ tf_raw,
                       const float* __restrict__ ms,
                       float* __restrict__ nms)
{
    const int m = threadIdx.x;
    const int c = blockIdx.x;
    const int b = blockIdx.y;
    const float td = sigmoidf_(td_raw[m]) * 0.9f + 0.1f;
    const float tf = sigmoidf_(tf_raw[m]);
    const float msterm = ms[b * M_ + m] * tf;

    // fused carry prefix: P_c = sum_{j<c} tdL^{c-1-j} carry_j
    const float tdL = powf(td, (float)LCH);
    float P = 0.0f;
#pragma unroll 4
    for (int j = 0; j < c; ++j)
        P = fmaf(tdL, P, g_carry[(b * CCH + j) * M_ + m]);

    size_t base = ((size_t)(b * S_ + c * LCH)) * M_ + m;
    float pw = td;
    float w = 0.0f;
#pragma unroll 4
    for (int i = 0; i < LCH; ++i) {
        w = g_wv[base + (size_t)i * M_] + P * pw + msterm;
        g_wv_h[base + (size_t)i * M_] = __float2half(w);
        pw *= td;
    }
    if (nms != nullptr && c == CCH - 1) nms[b * M_ + m] = w;
}

// ---------------------------------------------------------------------------
extern "C" void kernel_launch(void* const* d_in, const int* in_sizes, int n_in,
                              void* d_out, int out_size)
{
    const float* x   = (const float*)d_in[0];
    const float* ms  = (const float*)d_in[1];
    // d_in[2]=Wk, d_in[3]=bk: dead in the reference, intentionally unused
    const float* Wv  = (const float*)d_in[4];
    const float* bv  = (const float*)d_in[5];
    const float* Wg  = (const float*)d_in[6];
    const float* bg  = (const float*)d_in[7];
    const float* tdr = (const float*)d_in[8];
    const float* tfr = (const float*)d_in[9];
    float* out = (float*)d_out;

    float*  wv_ptr  = nullptr;
    __half* wvh_ptr = nullptr;
    __half* xh_ptr  = nullptr;
    __half* Wvh_ptr = nullptr;
    __half* Wgh_ptr = nullptr;
    cudaGetSymbolAddress((void**)&wv_ptr,  g_wv);
    cudaGetSymbolAddress((void**)&wvh_ptr, g_wv_h);
    cudaGetSymbolAddress((void**)&xh_ptr,  g_xh);
    cudaGetSymbolAddress((void**)&Wvh_ptr, g_Wvh);
    cudaGetSymbolAddress((void**)&Wgh_ptr, g_Wgh);

    const int DSMEM1 = 6 * 16384;  // GEMM1: 6 stages, 96KB
    const int DSMEM2 = 4 * 16384;  // GEMM2: 4 stages, 64KB
    cudaFuncSetAttribute((const void*)gemm_h<6, false, false>,
                         cudaFuncAttributeMaxDynamicSharedMemorySize, DSMEM1);
    cudaFuncSetAttribute((const void*)gemm_h<4, true, true>,
                         cudaFuncAttributeMaxDynamicSharedMemorySize, DSMEM2);

    // 0) fp32 -> fp16 operand conversion
    const int nx = BSR * D_, nwv = M_ * D_, nwg = D_ * (D_ + M_);
    cvt_f2h<<<(nx  + 2047) / 2048, 256>>>(x,  xh_ptr,  nx);
    cvt_f2h<<<(nwv + 2047) / 2048, 256>>>(Wv, Wvh_ptr, nwv);
    cvt_f2h<<<(nwg + 2047) / 2048, 256>>>(Wg, Wgh_ptr, nwg);

    // 1) v = x @ Wv^T + bv  -> g_wv (fp32)   [16384 x 512], K=2048
    gemm_h<6, false, false><<<dim3(M_ / 128, BSR / 128), 256, DSMEM1>>>(
        xh_ptr, D_, D_, nullptr, 0, Wvh_ptr, bv, nullptr, 0, wv_ptr, M_, D_);

    // 2) chunked scan + ms*tf -> g_wv_h (fp16), emits next_memory_state
    const size_t bsd = (size_t)B_ * S_ * D_;
    float* nms = ((size_t)out_size >= bsd + (size_t)B_ * M_) ? out + bsd : nullptr;
    scan_local_kernel<<<dim3(CCH, B_), M_>>>(tdr);
    scan_apply_kernel<<<dim3(CCH, B_), M_>>>(tdr, tfr, ms, nms);

    // 3) out = x + [x | wv] @ Wg^T + bg   [16384 x 2048], K=2560 (2048+512)
    gemm_h<4, true, true><<<dim3(D_ / 128, BSR / 128), 256, DSMEM2>>>(
        xh_ptr, D_, D_, wvh_ptr, M_, Wgh_ptr, bg, x, D_, out, D_, D_ + M_);
}

// round 17
// speedup vs baseline: 1.1055x; 1.0171x over previous
#include <cuda_runtime.h>
#include <cuda_fp16.h>
#include <cstdint>
#include <cstddef>

// ---------------------------------------------------------------------------
// StructuredStateRecurrence (sm_103 base -> legacy mma.sync path, fp16 HMMA).
//   v = x @ Wv^T + bv ; s_t = td*s_{t-1} + v_t ; wv = s + ms*tf
//   out = x + [x | wv] @ Wg^T + bg ; next_ms = wv[:, -1]
// k = x@Wk+bk is dead code in the reference -> skipped.
// R16: R15 (6-stage GEMM1 / 4-stage GEMM2 / fused 2-kernel scan) plus:
//      (1) GEMM2 residual read from fp16 x (halves the 134MB resid stream;
//          residual rounding ~2.4e-4 stays well inside the 1e-3 budget);
//      (2) the three fp32->fp16 cvt launches fused into one.
// Shapes: B=4, S=4096, D=2048, M=512.
// ---------------------------------------------------------------------------

#define B_  4
#define S_  4096
#define D_  2048
#define M_  512
#define BSR (B_ * S_)        // 16384 GEMM rows
#define CCH 128              // scan chunks
#define LCH (S_ / CCH)       // 32 steps per chunk

__device__ float  g_wv[(size_t)B_ * S_ * M_];      // fp32 v / scanned s
__device__ __half g_wv_h[(size_t)B_ * S_ * M_];    // fp16 wv for GEMM2
__device__ __half g_xh[(size_t)BSR * D_];          // fp16 x
__device__ __half g_Wvh[(size_t)M_ * D_];          // fp16 Wv
__device__ __half g_Wgh[(size_t)D_ * (D_ + M_)];   // fp16 Wg
__device__ float  g_carry[B_ * CCH * M_];

// ---------------- helpers ----------------
__device__ __forceinline__ unsigned pack_h2(float a, float b) {
    unsigned u;
    asm("cvt.rn.f16x2.f32 %0, %2, %1;" : "=r"(u) : "f"(a), "f"(b));
    return u;
}
__device__ __forceinline__ uint32_t smem_u32(const void* p) {
    uint32_t a;
    asm("{ .reg .u64 t; cvta.to.shared.u64 t, %1; cvt.u32.u64 %0, t; }"
        : "=r"(a) : "l"(p));
    return a;
}
__device__ __forceinline__ void cp16(uint32_t dst, const void* src) {
    asm volatile("cp.async.cg.shared.global [%0], [%1], 16;"
                 :: "r"(dst), "l"(src));
}
__device__ __forceinline__ void cp_commit() {
    asm volatile("cp.async.commit_group;");
}
template <int N>
__device__ __forceinline__ void cp_wait() {
    asm volatile("cp.async.wait_group %0;" :: "n"(N));
}
__device__ __forceinline__ void ldsm4(unsigned& r0, unsigned& r1,
                                      unsigned& r2, unsigned& r3, unsigned addr) {
    asm volatile("ldmatrix.sync.aligned.m8n8.x4.shared.b16 {%0,%1,%2,%3}, [%4];"
                 : "=r"(r0), "=r"(r1), "=r"(r2), "=r"(r3) : "r"(addr));
}
__device__ __forceinline__ void mma_fp16(float (&c)[4], const unsigned (&a)[4],
                                         const unsigned (&b)[2]) {
    asm volatile(
        "mma.sync.aligned.m16n8k16.row.col.f32.f16.f16.f32 "
        "{%0,%1,%2,%3}, {%4,%5,%6,%7}, {%8,%9}, {%0,%1,%2,%3};\n"
        : "+f"(c[0]), "+f"(c[1]), "+f"(c[2]), "+f"(c[3])
        : "r"(a[0]), "r"(a[1]), "r"(a[2]), "r"(a[3]), "r"(b[0]), "r"(b[1]));
}
__device__ __forceinline__ float sigmoidf_(float t) {
    return 1.0f / (1.0f + expf(-t));
}

// fused fp32 -> fp16 bulk convert over three concatenated arrays
__global__ __launch_bounds__(256)
void cvt_f2h3(const float* __restrict__ s0, __half* __restrict__ d0, int n0,
              const float* __restrict__ s1, __half* __restrict__ d1, int n1,
              const float* __restrict__ s2, __half* __restrict__ d2, int n2)
{
    int i = (blockIdx.x * 256 + threadIdx.x) * 8;
    const float* s;
    __half* d;
    if (i < n0)            { s = s0;          d = d0;          }
    else if (i < n0 + n1)  { s = s1; i -= n0; d = d1;          }
    else if (i < n0 + n1 + n2) { s = s2; i -= n0 + n1; d = d2; }
    else return;
    float4 a = *(const float4*)(s + i);
    float4 b = *(const float4*)(s + i + 4);
    *(uint4*)(d + i) = make_uint4(pack_h2(a.x, a.y), pack_h2(a.z, a.w),
                                  pack_h2(b.x, b.y), pack_h2(b.z, b.w));
}

// ---------------------------------------------------------------------------
// fp16 GEMM: C[row,n] = sum_k A[row,k]*Bm[n,k] + bias[n] (+ residH[row,n])
// A = virtual concat A1(K1)|A2 (K-tiles of 32 never straddle; K1 % 32 == 0).
// CTA tile 128x128, BK=32, 256 threads (8 warps, 2x4), warp tile 64x32
// (4x4 m16n8k16 frags), fp32 acc, occupancy 2. STG-stage cp.async pipeline
// (wait_group STG-2); stage = A[128][32h] (8KB) + B[128][32h] (8KB) = 16KB.
// Row = 64B = 4 x 16B chunks, chunk swizzle c ^= (row>>1)&3; fragments via
// ldmatrix.x4; cp.async issue interleaved between the two k16 halves.
// Residual (if any) is read as fp16 (half the stream of fp32).
// ---------------------------------------------------------------------------
template <int STG, bool HAS_A2, bool HAS_RES>
__global__ __launch_bounds__(256, 2)
void gemm_h(const __half* __restrict__ A1, int lda1, int K1,
            const __half* __restrict__ A2, int lda2,
            const __half* __restrict__ Bm,    // [N, Ktot] half, row-major
            const float* __restrict__ bias,   // [N]
            const __half* __restrict__ residH, int ldr,
            float* __restrict__ Cout, int ldc, int Ktot)
{
    extern __shared__ uint4 dsm4[];
    unsigned* smem = (unsigned*)dsm4;
    const unsigned sbase = smem_u32(smem);

    const int tid = threadIdx.x;
    const int lane = tid & 31;
    const int warp = tid >> 5;
    const int wm = (warp & 1) * 64;
    const int wn = (warp >> 1) * 32;
    const int rowBlock = blockIdx.y * 128;
    const int colBlock = blockIdx.x * 128;
    const int KT = Ktot / 32;

    // cp.async geometry: thread -> (row r, K-half h); 2 x 16B for A, 2 for B
    const int r = tid >> 1;       // 0..127
    const int h = tid & 1;        // 0..1
    const int swz = (r >> 1) & 3;
    const unsigned dA0 = sbase + (unsigned)(r * 64 + (((2 * h) ^ swz) << 4));
    const unsigned dA1 = sbase + (unsigned)(r * 64 + (((2 * h + 1) ^ swz) << 4));

    // ldmatrix per-lane geometry (j = lane>>3 selects the 8x8 matrix):
    //   A matrices: (r0,k-even),(r8,k-even),(r0,k-odd),(r8,k-odd)
    //   B matrices: (n0,k-even),(n0,k-odd),(n8,k-even),(n8,k-odd) per p
    const int lrow8 = lane & 7;
    unsigned offA[4], swzA[4];
#pragma unroll
    for (int mi = 0; mi < 4; ++mi) {
        const int rowA = wm + mi * 16 + (((lane >> 3) & 1) << 3) + lrow8;
        offA[mi] = (unsigned)(rowA * 64);
        swzA[mi] = (unsigned)((rowA >> 1) & 3);
    }
    const unsigned kselA = (unsigned)(lane >> 4);
    unsigned offB[2], swzB[2];
#pragma unroll
    for (int p = 0; p < 2; ++p) {
        const int rowB = wn + ((2 * p + (lane >> 4)) << 3) + lrow8;
        offB[p] = (unsigned)(rowB * 64);
        swzB[p] = (unsigned)((rowB >> 1) & 3);
    }
    const unsigned kselB = (unsigned)((lane >> 3) & 1);

    float acc[4][4][4];
#pragma unroll
    for (int i = 0; i < 4; ++i)
#pragma unroll
        for (int j = 0; j < 4; ++j)
#pragma unroll
            for (int q = 0; q < 4; ++q) acc[i][j][q] = 0.0f;

    auto issue = [&](int slot, int kt) {
        const int kBase = kt * 32;
        const __half* Ap = A1;
        int lda = lda1, kl = kBase;
        if (HAS_A2 && kBase >= K1) { Ap = A2; lda = lda2; kl = kBase - K1; }
        const char* ga = (const char*)(Ap + (size_t)(rowBlock + r) * lda + kl + h * 16);
        const char* gb = (const char*)(Bm + (size_t)(colBlock + r) * Ktot + kBase + h * 16);
        const unsigned so = (unsigned)(slot * 16384);
        cp16(dA0 + so, ga);
        cp16(dA1 + so, ga + 16);
        cp16(dA0 + so + 8192, gb);
        cp16(dA1 + so + 8192, gb + 16);
    };

    // one k16 step (ks in 0..1) of the K-tile in `slot`
    auto compute_ks = [&](int slot, int ks) {
        const unsigned baseA = sbase + (unsigned)(slot * 16384);
        const unsigned baseB = baseA + 8192u;
        const unsigned kgA = 2u * (unsigned)ks + kselA;
        const unsigned kgB = 2u * (unsigned)ks + kselB;
        unsigned a[4][4], bfr[4][2];
#pragma unroll
        for (int mi = 0; mi < 4; ++mi)
            ldsm4(a[mi][0], a[mi][1], a[mi][2], a[mi][3],
                  baseA + offA[mi] + ((kgA ^ swzA[mi]) << 4));
#pragma unroll
        for (int p = 0; p < 2; ++p)
            ldsm4(bfr[2 * p][0], bfr[2 * p][1], bfr[2 * p + 1][0], bfr[2 * p + 1][1],
                  baseB + offB[p] + ((kgB ^ swzB[p]) << 4));
#pragma unroll
        for (int mi = 0; mi < 4; ++mi)
#pragma unroll
            for (int ni = 0; ni < 4; ++ni) mma_fp16(acc[mi][ni], a[mi], bfr[ni]);
    };

    // prologue: stages 0..STG-2
#pragma unroll
    for (int s = 0; s < STG - 1; ++s) { issue(s, s); cp_commit(); }

    for (int kt = 0; kt < KT; ++kt) {
        cp_wait<STG - 2>();    // pending <= STG-2 -> tile kt resident
        __syncthreads();       // also protects slot reuse
        const int cur = kt % STG;
        // first k16 half starts the MMA stream immediately...
        compute_ks(cur, 0);
        // ...then next tile's cp.async issue dual-issues under the MMAs
        const int pf = kt + STG - 1;
        if (pf < KT) issue(pf % STG, pf);
        cp_commit();
        compute_ks(cur, 1);
    }

    // epilogue: bias + optional fp16 residual, float2 stores (col even)
#pragma unroll
    for (int mi = 0; mi < 4; ++mi) {
#pragma unroll
        for (int ni = 0; ni < 4; ++ni) {
            const int row = rowBlock + wm + mi * 16 + (lane >> 2);
            const int col = colBlock + wn + ni * 8 + (lane & 3) * 2;
            const float b0v = bias[col];
            const float b1v = bias[col + 1];
            float r00 = 0.f, r01 = 0.f, r10 = 0.f, r11 = 0.f;
            if (HAS_RES) {
                const __half2 q0 = *(const __half2*)(residH + (size_t)row * ldr + col);
                const __half2 q1 = *(const __half2*)(residH + (size_t)(row + 8) * ldr + col);
                const float2 f0 = __half22float2(q0);
                const float2 f1 = __half22float2(q1);
                r00 = f0.x; r01 = f0.y; r10 = f1.x; r11 = f1.y;
            }
            *(float2*)(Cout + (size_t)row * ldc + col) =
                make_float2(acc[mi][ni][0] + b0v + r00, acc[mi][ni][1] + b1v + r01);
            *(float2*)(Cout + (size_t)(row + 8) * ldc + col) =
                make_float2(acc[mi][ni][2] + b0v + r10, acc[mi][ni][3] + b1v + r11);
        }
    }
}

// ---------------------------------------------------------------------------
// Chunked linear-recurrence scan (2 passes, fused carry — measured -18.5us).
// ---------------------------------------------------------------------------
__global__ __launch_bounds__(M_)
void scan_local_kernel(const float* __restrict__ td_raw)
{
    const int m = threadIdx.x;
    const int c = blockIdx.x;
    const int b = blockIdx.y;
    const float td = sigmoidf_(td_raw[m]) * 0.9f + 0.1f;
    size_t base = ((size_t)(b * S_ + c * LCH)) * M_ + m;
    float s = 0.0f;
#pragma unroll 4
    for (int i = 0; i < LCH; ++i) {
        const float v = g_wv[base + (size_t)i * M_];
        s = fmaf(td, s, v);
        g_wv[base + (size_t)i * M_] = s;
    }
    g_carry[(b * CCH + c) * M_ + m] = s;
}

// wv = local + P*td^(i+1) + ms*tf -> fp16 for GEMM2; nms (fp32) at t=S-1
__global__ __launch_bounds__(M_)
void scan_apply_kernel(const float* __restrict__ td_raw,
                       const float* __restrict__ tf_raw,
                       const float* __restrict__ ms,
                       float* __restrict__ nms)
{
    const int m = threadIdx.x;
    const int c = blockIdx.x;
    const int b = blockIdx.y;
    const float td = sigmoidf_(td_raw[m]) * 0.9f + 0.1f;
    const float tf = sigmoidf_(tf_raw[m]);
    const float msterm = ms[b * M_ + m] * tf;

    // fused carry prefix: P_c = sum_{j<c} tdL^{c-1-j} carry_j
    const float tdL = powf(td, (float)LCH);
    float P = 0.0f;
#pragma unroll 4
    for (int j = 0; j < c; ++j)
        P = fmaf(tdL, P, g_carry[(b * CCH + j) * M_ + m]);

    size_t base = ((size_t)(b * S_ + c * LCH)) * M_ + m;
    float pw = td;
    float w = 0.0f;
#pragma unroll 4
    for (int i = 0; i < LCH; ++i) {
        w = g_wv[base + (size_t)i * M_] + P * pw + msterm;
        g_wv_h[base + (size_t)i * M_] = __float2half(w);
        pw *= td;
    }
    if (nms != nullptr && c == CCH - 1) nms[b * M_ + m] = w;
}

// ---------------------------------------------------------------------------
extern "C" void kernel_launch(void* const* d_in, const int* in_sizes, int n_in,
                              void* d_out, int out_size)
{
    const float* x   = (const float*)d_in[0];
    const float* ms  = (const float*)d_in[1];
    // d_in[2]=Wk, d_in[3]=bk: dead in the reference, intentionally unused
    const float* Wv  = (const float*)d_in[4];
    const float* bv  = (const float*)d_in[5];
    const float* Wg  = (const float*)d_in[6];
    const float* bg  = (const float*)d_in[7];
    const float* tdr = (const float*)d_in[8];
    const float* tfr = (const float*)d_in[9];
    float* out = (float*)d_out;

    float*  wv_ptr  = nullptr;
    __half* wvh_ptr = nullptr;
    __half* xh_ptr  = nullptr;
    __half* Wvh_ptr = nullptr;
    __half* Wgh_ptr = nullptr;
    cudaGetSymbolAddress((void**)&wv_ptr,  g_wv);
    cudaGetSymbolAddress((void**)&wvh_ptr, g_wv_h);
    cudaGetSymbolAddress((void**)&xh_ptr,  g_xh);
    cudaGetSymbolAddress((void**)&Wvh_ptr, g_Wvh);
    cudaGetSymbolAddress((void**)&Wgh_ptr, g_Wgh);

    const int DSMEM1 = 6 * 16384;  // GEMM1: 6 stages, 96KB
    const int DSMEM2 = 4 * 16384;  // GEMM2: 4 stages, 64KB
    cudaFuncSetAttribute((const void*)gemm_h<6, false, false>,
                         cudaFuncAttributeMaxDynamicSharedMemorySize, DSMEM1);
    cudaFuncSetAttribute((const void*)gemm_h<4, true, true>,
                         cudaFuncAttributeMaxDynamicSharedMemorySize, DSMEM2);

    // 0) fp32 -> fp16 operand conversion (single fused launch)
    const int nx = BSR * D_, nwv = M_ * D_, nwg = D_ * (D_ + M_);
    const int ncvt = nx + nwv + nwg;
    cvt_f2h3<<<(ncvt + 2047) / 2048, 256>>>(x, xh_ptr, nx,
                                            Wv, Wvh_ptr, nwv,
                                            Wg, Wgh_ptr, nwg);

    // 1) v = x @ Wv^T + bv  -> g_wv (fp32)   [16384 x 512], K=2048
    gemm_h<6, false, false><<<dim3(M_ / 128, BSR / 128), 256, DSMEM1>>>(
        xh_ptr, D_, D_, nullptr, 0, Wvh_ptr, bv, nullptr, 0, wv_ptr, M_, D_);

    // 2) chunked scan + ms*tf -> g_wv_h (fp16), emits next_memory_state
    const size_t bsd = (size_t)B_ * S_ * D_;
    float* nms = ((size_t)out_size >= bsd + (size_t)B_ * M_) ? out + bsd : nullptr;
    scan_local_kernel<<<dim3(CCH, B_), M_>>>(tdr);
    scan_apply_kernel<<<dim3(CCH, B_), M_>>>(tdr, tfr, ms, nms);

    // 3) out = x + [x | wv] @ Wg^T + bg   [16384 x 2048], K=2560 (2048+512)
    //    residual read from fp16 x (halves the resid DRAM stream)
    gemm_h<4, true, true><<<dim3(D_ / 128, BSR / 128), 256, DSMEM2>>>(
        xh_ptr, D_, D_, wvh_ptr, M_, Wgh_ptr, bg, xh_ptr, D_, out, D_, D_ + M_);
}